// round 15
// baseline (speedup 1.0000x reference)
#include <cuda_runtime.h>
#include <cuda_bf16.h>
#include <cstdint>
#include <cstring>

#define BATCH 8192
#define NIN   3072
#define NOUT  512
#define EPSF  1e-20f
#define NITER 5
#define MT    32     // rows per block
#define NB    256    // blocks — 2/SM co-resident (grid barrier safe: 256 <= 148*2)
#define T     256    // threads (8 warps; 1x8 warp grid over 32x128 tile)
#define NCH   128    // N-chunk
#define KC    64     // k-chunk

// ---- gmem scratch (allocation-free rule) -----------------------------------
__device__ __nv_bfloat16 g_whi[(size_t)NOUT * NIN], g_wlo[(size_t)NOUT * NIN];   // W  [n][j]
__device__ __nv_bfloat16 g_wthi[(size_t)NIN * NOUT], g_wtlo[(size_t)NIN * NOUT]; // W^T[j][n]
__device__ __nv_bfloat16 g_hhi[(size_t)BATCH * NOUT], g_hlo[(size_t)BATCH * NOUT];
__device__ __nv_bfloat16 g_rhi[(size_t)BATCH * NIN], g_rlo[(size_t)BATCH * NIN];
__device__ float g_h[(size_t)BATCH * NOUT];
__device__ unsigned g_bar;

// ---- smem: double-buffered stages; rows padded to 144B ----------------------
#define RS_A   144
#define A_HI   0
#define A_LO   (MT * RS_A)             //  4608
#define B_HI   (2 * MT * RS_A)         //  9216
#define B_LO   (B_HI + 128 * RS_A)     // 27648
#define STAGE  (B_LO + 128 * RS_A)     // 46080
#define SM_XINV (2 * STAGE)            // 92160
#define SM_RS   (SM_XINV + MT * 4)
#define SM_SC   (SM_RS + MT * 4)
#define SM_TOTAL (SM_SC + MT * 4)      // 92544  -> 2 blocks/SM

__device__ __forceinline__ void bf_split(float v, uint16_t& hi, uint16_t& lo) {
    __nv_bfloat16 h = __float2bfloat16_rn(v);
    __nv_bfloat16 l = __float2bfloat16_rn(v - __bfloat162float(h));
    memcpy(&hi, &h, 2); memcpy(&lo, &l, 2);
}
__device__ __forceinline__ uint32_t smem_u32(const void* p) {
    uint32_t a;
    asm("{ .reg .u64 t; cvta.to.shared.u64 t, %1; cvt.u32.u64 %0, t; }" : "=r"(a) : "l"(p));
    return a;
}
__device__ __forceinline__ void cp16(uint32_t saddr, const void* g) {
    asm volatile("cp.async.cg.shared.global [%0], [%1], 16;" :: "r"(saddr), "l"(g));
}
#define CP_COMMIT() asm volatile("cp.async.commit_group;" ::: "memory")
#define CP_WAIT1()  asm volatile("cp.async.wait_group 1;" ::: "memory")
#define CP_WAIT0()  asm volatile("cp.async.wait_group 0;" ::: "memory")

__device__ __forceinline__ void mma_bf16(float c[4], const uint32_t a[4], const uint32_t b[2]) {
    asm volatile(
        "mma.sync.aligned.m16n8k16.row.col.f32.bf16.bf16.f32 "
        "{%0,%1,%2,%3}, {%4,%5,%6,%7}, {%8,%9}, {%0,%1,%2,%3};"
        : "+f"(c[0]), "+f"(c[1]), "+f"(c[2]), "+f"(c[3])
        : "r"(a[0]), "r"(a[1]), "r"(a[2]), "r"(a[3]), "r"(b[0]), "r"(b[1]));
}

// One 32x128x64 chunk: acc += Ahi*Bhi + Ahi*Blo + Alo*Bhi (split precision).
// Warp wn owns n-slice [wn*16, wn*16+16); warp tile 32m x 16n.
__device__ __forceinline__ void gemm_chunk(const char* sm, float acc[2][2][4],
                                           int lane, int wn) {
    const int mr = lane >> 2;
    const int kq = (lane & 3) * 4;
    #pragma unroll
    for (int ks = 0; ks < 4; ks++) {
        const int kb = ks * 32 + kq;
        uint32_t ah[2][4], al[2][4];
        #pragma unroll
        for (int mt = 0; mt < 2; mt++) {
            const int base = (mt * 16 + mr) * RS_A + kb;
            ah[mt][0] = *(const uint32_t*)(sm + A_HI + base);
            ah[mt][1] = *(const uint32_t*)(sm + A_HI + base + 8 * RS_A);
            ah[mt][2] = *(const uint32_t*)(sm + A_HI + base + 16);
            ah[mt][3] = *(const uint32_t*)(sm + A_HI + base + 8 * RS_A + 16);
            al[mt][0] = *(const uint32_t*)(sm + A_LO + base);
            al[mt][1] = *(const uint32_t*)(sm + A_LO + base + 8 * RS_A);
            al[mt][2] = *(const uint32_t*)(sm + A_LO + base + 16);
            al[mt][3] = *(const uint32_t*)(sm + A_LO + base + 8 * RS_A + 16);
        }
        #pragma unroll
        for (int nt = 0; nt < 2; nt++) {
            const int base = (wn * 16 + nt * 8 + mr) * RS_A + kb;
            uint32_t bh[2], bl[2];
            bh[0] = *(const uint32_t*)(sm + B_HI + base);
            bh[1] = *(const uint32_t*)(sm + B_HI + base + 16);
            bl[0] = *(const uint32_t*)(sm + B_LO + base);
            bl[1] = *(const uint32_t*)(sm + B_LO + base + 16);
            #pragma unroll
            for (int mt = 0; mt < 2; mt++) {
                mma_bf16(acc[mt][nt], ah[mt], bh);
                mma_bf16(acc[mt][nt], ah[mt], bl);
                mma_bf16(acc[mt][nt], al[mt], bh);
            }
        }
    }
}

__global__ __launch_bounds__(T, 2) void nnmf_mma_kernel(
    const float* __restrict__ x, const float* __restrict__ W,
    const float* __restrict__ h0, float* __restrict__ out
) {
    extern __shared__ __align__(16) char sm[];
    float* sxinv = (float*)(sm + SM_XINV);
    float* srs   = (float*)(sm + SM_RS);
    float* ssc   = (float*)(sm + SM_SC);
    const uint32_t sb = smem_u32(sm);

    const int tid = threadIdx.x, lane = tid & 31, warp = tid >> 5;
    const int wn = warp;                 // 1x8 warp grid
    const int r0 = blockIdx.x * MT;

    uint32_t* hhi32 = (uint32_t*)g_hhi;
    uint32_t* hlo32 = (uint32_t*)g_hlo;
    uint32_t* rhi32 = (uint32_t*)g_rhi;
    uint32_t* rlo32 = (uint32_t*)g_rlo;

    // ---- one-time W + W^T bf16 hi/lo split (grid-cooperative) ----
    for (size_t i = (size_t)blockIdx.x * T + tid; i < (size_t)NOUT * NIN; i += (size_t)NB * T) {
        const int n = (int)(i / NIN), j = (int)(i % NIN);
        uint16_t hi, lo;
        bf_split(W[i], hi, lo);
        memcpy(&g_whi[i], &hi, 2); memcpy(&g_wlo[i], &lo, 2);
        const size_t ti = (size_t)j * NOUT + n;
        memcpy(&g_wthi[ti], &hi, 2); memcpy(&g_wtlo[ti], &lo, 2);
    }
    // ---- block-private init ----
    for (int i = tid; i < MT * NOUT / 2; i += T) {
        const int row = i >> 8, c = i & 255;
        const float v0 = h0[c * 2], v1 = h0[c * 2 + 1];
        uint16_t h0b, l0b, h1b, l1b;
        bf_split(v0, h0b, l0b); bf_split(v1, h1b, l1b);
        const size_t gi = ((size_t)(r0 + row) * NOUT) / 2 + c;
        ((float2*)g_h)[gi] = make_float2(v0, v1);
        hhi32[gi] = ((uint32_t)h1b << 16) | h0b;
        hlo32[gi] = ((uint32_t)l1b << 16) | l0b;
    }
    for (int r = warp; r < MT; r += 8) {
        const float* xr = x + (size_t)(r0 + r) * NIN;
        float s = 0.f;
        for (int k = lane; k < NIN; k += 32) s += xr[k];
        #pragma unroll
        for (int o = 16; o; o >>= 1) s += __shfl_xor_sync(~0u, s, o);
        if (lane == 0) sxinv[r] = 1.0f / (s + EPSF);
    }
    __syncthreads();
    if (tid == 0) {   // grid barrier (256 co-resident blocks)
        __threadfence();
        unsigned old = atomicAdd(&g_bar, 1u);
        unsigned target = (old / NB + 1u) * NB;
        while (atomicAdd(&g_bar, 0u) < target) {}
        __threadfence();
    }
    __syncthreads();

    const int mr = lane >> 2, qc = (lane & 3) * 2;

    auto stage_g1 = [&](int kc, int buf, int j0) {
        const int n0 = kc * KC;
        const uint32_t sbase = sb + buf * STAGE;
        for (int idx = tid; idx < MT * 8; idx += T) {
            const int m = idx >> 3, ch = (idx & 7) * 16;
            const size_t gb = ((size_t)(r0 + m) * NOUT + n0) * 2 + ch;
            cp16(sbase + A_HI + m * RS_A + ch, (const char*)g_hhi + gb);
            cp16(sbase + A_LO + m * RS_A + ch, (const char*)g_hlo + gb);
        }
        for (int idx = tid; idx < 128 * 8; idx += T) {
            const int j = idx >> 3, ch = (idx & 7) * 16;
            const size_t gb = ((size_t)(j0 + j) * NOUT + n0) * 2 + ch;
            cp16(sbase + B_HI + j * RS_A + ch, (const char*)g_wthi + gb);
            cp16(sbase + B_LO + j * RS_A + ch, (const char*)g_wtlo + gb);
        }
        CP_COMMIT();
    };
    auto stage_g2 = [&](int kc, int buf, int nb) {
        const int k0 = kc * KC;
        const uint32_t sbase = sb + buf * STAGE;
        for (int idx = tid; idx < MT * 8; idx += T) {
            const int m = idx >> 3, ch = (idx & 7) * 16;
            const size_t gb = ((size_t)(r0 + m) * NIN + k0) * 2 + ch;
            cp16(sbase + A_HI + m * RS_A + ch, (const char*)g_rhi + gb);
            cp16(sbase + A_LO + m * RS_A + ch, (const char*)g_rlo + gb);
        }
        for (int idx = tid; idx < 128 * 8; idx += T) {
            const int n = idx >> 3, ch = (idx & 7) * 16;
            const size_t gb = ((size_t)(nb + n) * NIN + k0) * 2 + ch;
            cp16(sbase + B_HI + n * RS_A + ch, (const char*)g_whi + gb);
            cp16(sbase + B_LO + n * RS_A + ch, (const char*)g_wlo + gb);
        }
        CP_COMMIT();
    };

    for (int iter = 0; iter < NITER; iter++) {
        if (tid < MT) srs[tid] = 0.f;

        // ===== GEMM1: denom = h @ W (pipelined); epilogue -> ratio split
        for (int jc = 0; jc < NIN / NCH; jc++) {
            const int j0 = jc * NCH;
            float acc[2][2][4] = {};
            stage_g1(0, 0, j0);
            #pragma unroll 1
            for (int kc = 0; kc < NOUT / KC; kc++) {
                if (kc + 1 < NOUT / KC) { stage_g1(kc + 1, (kc + 1) & 1, j0); CP_WAIT1(); }
                else CP_WAIT0();
                __syncthreads();
                gemm_chunk(sm + (kc & 1) * STAGE, acc, lane, wn);
                __syncthreads();
            }
            #pragma unroll
            for (int mt = 0; mt < 2; mt++)
            #pragma unroll
            for (int half = 0; half < 2; half++) {
                const int row = mt * 16 + mr + half * 8;
                const float xiv = sxinv[row];
                const size_t rowbase = (size_t)(r0 + row) * NIN + j0;
                #pragma unroll
                for (int nt = 0; nt < 2; nt++) {
                    const int jl = wn * 16 + nt * 8 + qc;
                    const float c0 = acc[mt][nt][half * 2], c1 = acc[mt][nt][half * 2 + 1];
                    const float2 xv = *(const float2*)(x + rowbase + jl);
                    const float v0 = __fdividef(xv.x * xiv, c0 + EPSF);
                    const float v1 = __fdividef(xv.y * xiv, c1 + EPSF);
                    uint16_t h0b, l0b, h1b, l1b;
                    bf_split(v0, h0b, l0b); bf_split(v1, h1b, l1b);
                    rhi32[(rowbase + jl) >> 1] = ((uint32_t)h1b << 16) | h0b;
                    rlo32[(rowbase + jl) >> 1] = ((uint32_t)l1b << 16) | l0b;
                }
            }
        }
        __syncthreads();

        // ===== GEMM2: t = ratio @ W^T (pipelined); u = h*(1+t)
        for (int nc = 0; nc < NOUT / NCH; nc++) {
            const int nb = nc * NCH;
            float acc[2][2][4] = {};
            stage_g2(0, 0, nb);
            #pragma unroll 1
            for (int kc = 0; kc < NIN / KC; kc++) {
                if (kc + 1 < NIN / KC) { stage_g2(kc + 1, (kc + 1) & 1, nb); CP_WAIT1(); }
                else CP_WAIT0();
                __syncthreads();
                gemm_chunk(sm + (kc & 1) * STAGE, acc, lane, wn);
                __syncthreads();
            }
            #pragma unroll
            for (int mt = 0; mt < 2; mt++)
            #pragma unroll
            for (int half = 0; half < 2; half++) {
                const int row = mt * 16 + mr + half * 8;
                float partial = 0.f;
                #pragma unroll
                for (int nt = 0; nt < 2; nt++) {
                    const int cl = wn * 16 + nt * 8 + qc;
                    const float t0 = acc[mt][nt][half * 2], t1 = acc[mt][nt][half * 2 + 1];
                    const size_t gi = (size_t)(r0 + row) * NOUT + nb + cl;
                    const float2 hv = *(const float2*)(g_h + gi);
                    const float u0 = hv.x * (1.0f + t0), u1 = hv.y * (1.0f + t1);
                    *(float2*)(g_h + gi) = make_float2(u0, u1);
                    partial += u0 + u1;
                }
                atomicAdd(&srs[row], partial);
            }
        }
        __syncthreads();
        if (tid < MT) ssc[tid] = 1.0f / (srs[tid] + EPSF);
        __syncthreads();

        for (int i = tid; i < MT * NOUT / 2; i += T) {
            const int row = i >> 8, c = i & 255;
            const size_t gi = ((size_t)(r0 + row) * NOUT) / 2 + c;
            float2 hv = ((float2*)g_h)[gi];
            const float sc = ssc[row];
            hv.x *= sc; hv.y *= sc;
            ((float2*)g_h)[gi] = hv;
            uint16_t h0b, l0b, h1b, l1b;
            bf_split(hv.x, h0b, l0b); bf_split(hv.y, h1b, l1b);
            hhi32[gi] = ((uint32_t)h1b << 16) | h0b;
            hlo32[gi] = ((uint32_t)l1b << 16) | l0b;
            if (iter == NITER - 1) ((float2*)out)[gi] = hv;
        }
        __syncthreads();
    }
}

extern "C" void kernel_launch(void* const* d_in, const int* in_sizes, int n_in,
                              void* d_out, int out_size) {
    const float* x = nullptr;
    const float* W = nullptr;
    const float* h0 = nullptr;
    for (int i = 0; i < n_in; i++) {
        if (in_sizes[i] == BATCH * NIN)      x  = (const float*)d_in[i];
        else if (in_sizes[i] == NOUT * NIN)  W  = (const float*)d_in[i];
        else if (in_sizes[i] == NOUT)        h0 = (const float*)d_in[i];
    }
    float* out = (float*)d_out;

    cudaFuncSetAttribute(nnmf_mma_kernel,
                         cudaFuncAttributeMaxDynamicSharedMemorySize, SM_TOTAL);
    nnmf_mma_kernel<<<NB, T, SM_TOTAL>>>(x, W, h0, out);
}

// round 16
// speedup vs baseline: 1.1265x; 1.1265x over previous
#include <cuda_runtime.h>
#include <cuda_bf16.h>
#include <cstdint>
#include <cstring>

#define BATCH 8192
#define NIN   3072
#define NOUT  512
#define EPSF  1e-20f
#define NITER 5
#define MT    64     // rows per block
#define NB    128    // blocks — one wave, co-resident (grid barrier safe)
#define T     256    // threads (8 warps; 2x4 warp grid over 64x128 tile)
#define NCH   128    // N-chunk
#define KC    64     // k-chunk

// ---- gmem scratch (allocation-free rule) -----------------------------------
__device__ __nv_bfloat16 g_whi[(size_t)NOUT * NIN], g_wlo[(size_t)NOUT * NIN];   // W  [n][j]
__device__ __nv_bfloat16 g_wthi[(size_t)NIN * NOUT], g_wtlo[(size_t)NIN * NOUT]; // W^T[j][n]
__device__ __nv_bfloat16 g_hhi[(size_t)BATCH * NOUT], g_hlo[(size_t)BATCH * NOUT];
__device__ __nv_bfloat16 g_rhi[(size_t)BATCH * NIN], g_rlo[(size_t)BATCH * NIN];
__device__ float g_h[(size_t)BATCH * NOUT];
__device__ unsigned g_bar;

// ---- smem: 3-stage cp.async ring; rows padded to 144B -----------------------
#define RS_A   144
#define A_HI   0
#define A_LO   (64 * RS_A)             //  9216
#define B_HI   (2 * 64 * RS_A)         // 18432
#define B_LO   (B_HI + 128 * RS_A)     // 36864
#define STAGE  (B_LO + 128 * RS_A)     // 55296
#define NSTG   3
#define SM_XINV (NSTG * STAGE)         // 165888
#define SM_RS   (SM_XINV + 64 * 4)
#define SM_SC   (SM_RS + 64 * 4)
#define SM_TOTAL (SM_SC + 64 * 4)      // 166656 -> 1 block/SM

__device__ __forceinline__ void bf_split(float v, uint16_t& hi, uint16_t& lo) {
    __nv_bfloat16 h = __float2bfloat16_rn(v);
    __nv_bfloat16 l = __float2bfloat16_rn(v - __bfloat162float(h));
    memcpy(&hi, &h, 2); memcpy(&lo, &l, 2);
}
__device__ __forceinline__ uint32_t smem_u32(const void* p) {
    uint32_t a;
    asm("{ .reg .u64 t; cvta.to.shared.u64 t, %1; cvt.u32.u64 %0, t; }" : "=r"(a) : "l"(p));
    return a;
}
__device__ __forceinline__ void cp16(uint32_t saddr, const void* g) {
    asm volatile("cp.async.cg.shared.global [%0], [%1], 16;" :: "r"(saddr), "l"(g));
}
#define CP_COMMIT() asm volatile("cp.async.commit_group;" ::: "memory")
#define CP_WAIT1()  asm volatile("cp.async.wait_group 1;" ::: "memory")
#define CP_WAIT0()  asm volatile("cp.async.wait_group 0;" ::: "memory")

__device__ __forceinline__ void mma_bf16(float c[4], const uint32_t a[4], const uint32_t b[2]) {
    asm volatile(
        "mma.sync.aligned.m16n8k16.row.col.f32.bf16.bf16.f32 "
        "{%0,%1,%2,%3}, {%4,%5,%6,%7}, {%8,%9}, {%0,%1,%2,%3};"
        : "+f"(c[0]), "+f"(c[1]), "+f"(c[2]), "+f"(c[3])
        : "r"(a[0]), "r"(a[1]), "r"(a[2]), "r"(a[3]), "r"(b[0]), "r"(b[1]));
}

// One 64x128x64 chunk: acc += Ahi*Bhi + Ahi*Blo + Alo*Bhi (split precision).
__device__ __forceinline__ void gemm_chunk(const char* sm, float acc[2][4][4],
                                           int lane, int wm, int wn) {
    const int mr = lane >> 2;
    const int kq = (lane & 3) * 4;
    #pragma unroll
    for (int ks = 0; ks < 4; ks++) {
        const int kb = ks * 32 + kq;
        uint32_t ah[2][4], al[2][4];
        #pragma unroll
        for (int mt = 0; mt < 2; mt++) {
            const int base = (wm * 32 + mt * 16 + mr) * RS_A + kb;
            ah[mt][0] = *(const uint32_t*)(sm + A_HI + base);
            ah[mt][1] = *(const uint32_t*)(sm + A_HI + base + 8 * RS_A);
            ah[mt][2] = *(const uint32_t*)(sm + A_HI + base + 16);
            ah[mt][3] = *(const uint32_t*)(sm + A_HI + base + 8 * RS_A + 16);
            al[mt][0] = *(const uint32_t*)(sm + A_LO + base);
            al[mt][1] = *(const uint32_t*)(sm + A_LO + base + 8 * RS_A);
            al[mt][2] = *(const uint32_t*)(sm + A_LO + base + 16);
            al[mt][3] = *(const uint32_t*)(sm + A_LO + base + 8 * RS_A + 16);
        }
        #pragma unroll
        for (int nt = 0; nt < 4; nt++) {
            const int base = (wn * 32 + nt * 8 + mr) * RS_A + kb;
            uint32_t bh[2], bl[2];
            bh[0] = *(const uint32_t*)(sm + B_HI + base);
            bh[1] = *(const uint32_t*)(sm + B_HI + base + 16);
            bl[0] = *(const uint32_t*)(sm + B_LO + base);
            bl[1] = *(const uint32_t*)(sm + B_LO + base + 16);
            #pragma unroll
            for (int mt = 0; mt < 2; mt++) {
                mma_bf16(acc[mt][nt], ah[mt], bh);
                mma_bf16(acc[mt][nt], ah[mt], bl);
                mma_bf16(acc[mt][nt], al[mt], bh);
            }
        }
    }
}

__global__ __launch_bounds__(T, 1) void nnmf_mma_kernel(
    const float* __restrict__ x, const float* __restrict__ W,
    const float* __restrict__ h0, float* __restrict__ out
) {
    extern __shared__ __align__(16) char sm[];
    float* sxinv = (float*)(sm + SM_XINV);
    float* srs   = (float*)(sm + SM_RS);
    float* ssc   = (float*)(sm + SM_SC);
    const uint32_t sb = smem_u32(sm);

    const int tid = threadIdx.x, lane = tid & 31, warp = tid >> 5;
    const int wm = warp >> 2, wn = warp & 3;
    const int r0 = blockIdx.x * MT;

    uint32_t* hhi32 = (uint32_t*)g_hhi;
    uint32_t* hlo32 = (uint32_t*)g_hlo;
    uint32_t* rhi32 = (uint32_t*)g_rhi;
    uint32_t* rlo32 = (uint32_t*)g_rlo;

    // ---- one-time W + W^T bf16 hi/lo split (grid-cooperative) ----
    for (size_t i = (size_t)blockIdx.x * T + tid; i < (size_t)NOUT * NIN; i += (size_t)NB * T) {
        const int n = (int)(i / NIN), j = (int)(i % NIN);
        uint16_t hi, lo;
        bf_split(W[i], hi, lo);
        memcpy(&g_whi[i], &hi, 2); memcpy(&g_wlo[i], &lo, 2);
        const size_t ti = (size_t)j * NOUT + n;
        memcpy(&g_wthi[ti], &hi, 2); memcpy(&g_wtlo[ti], &lo, 2);
    }
    // ---- block-private init ----
    for (int i = tid; i < MT * NOUT / 2; i += T) {
        const int row = i >> 8, c = i & 255;
        const float v0 = h0[c * 2], v1 = h0[c * 2 + 1];
        uint16_t h0b, l0b, h1b, l1b;
        bf_split(v0, h0b, l0b); bf_split(v1, h1b, l1b);
        const size_t gi = ((size_t)(r0 + row) * NOUT) / 2 + c;
        ((float2*)g_h)[gi] = make_float2(v0, v1);
        hhi32[gi] = ((uint32_t)h1b << 16) | h0b;
        hlo32[gi] = ((uint32_t)l1b << 16) | l0b;
    }
    for (int r = warp; r < MT; r += 8) {
        const float* xr = x + (size_t)(r0 + r) * NIN;
        float s = 0.f;
        for (int k = lane; k < NIN; k += 32) s += xr[k];
        #pragma unroll
        for (int o = 16; o; o >>= 1) s += __shfl_xor_sync(~0u, s, o);
        if (lane == 0) sxinv[r] = 1.0f / (s + EPSF);
    }
    __syncthreads();
    if (tid == 0) {   // grid barrier (128 co-resident blocks)
        __threadfence();
        unsigned old = atomicAdd(&g_bar, 1u);
        unsigned target = (old / NB + 1u) * NB;
        while (atomicAdd(&g_bar, 0u) < target) {}
        __threadfence();
    }
    __syncthreads();

    const int mr = lane >> 2, qc = (lane & 3) * 2;

    auto stage_g1 = [&](int kc, int buf, int j0) {
        const int n0 = kc * KC;
        const uint32_t sbase = sb + buf * STAGE;
        for (int idx = tid; idx < 64 * 8; idx += T) {
            const int m = idx >> 3, ch = (idx & 7) * 16;
            const size_t gb = ((size_t)(r0 + m) * NOUT + n0) * 2 + ch;
            cp16(sbase + A_HI + m * RS_A + ch, (const char*)g_hhi + gb);
            cp16(sbase + A_LO + m * RS_A + ch, (const char*)g_hlo + gb);
        }
        for (int idx = tid; idx < 128 * 8; idx += T) {
            const int j = idx >> 3, ch = (idx & 7) * 16;
            const size_t gb = ((size_t)(j0 + j) * NOUT + n0) * 2 + ch;
            cp16(sbase + B_HI + j * RS_A + ch, (const char*)g_wthi + gb);
            cp16(sbase + B_LO + j * RS_A + ch, (const char*)g_wtlo + gb);
        }
        CP_COMMIT();
    };
    auto stage_g2 = [&](int kc, int buf, int nb) {
        const int k0 = kc * KC;
        const uint32_t sbase = sb + buf * STAGE;
        for (int idx = tid; idx < 64 * 8; idx += T) {
            const int m = idx >> 3, ch = (idx & 7) * 16;
            const size_t gb = ((size_t)(r0 + m) * NIN + k0) * 2 + ch;
            cp16(sbase + A_HI + m * RS_A + ch, (const char*)g_rhi + gb);
            cp16(sbase + A_LO + m * RS_A + ch, (const char*)g_rlo + gb);
        }
        for (int idx = tid; idx < 128 * 8; idx += T) {
            const int n = idx >> 3, ch = (idx & 7) * 16;
            const size_t gb = ((size_t)(nb + n) * NIN + k0) * 2 + ch;
            cp16(sbase + B_HI + n * RS_A + ch, (const char*)g_whi + gb);
            cp16(sbase + B_LO + n * RS_A + ch, (const char*)g_wlo + gb);
        }
        CP_COMMIT();
    };

    for (int iter = 0; iter < NITER; iter++) {
        if (tid < MT) srs[tid] = 0.f;

        // ===== GEMM1: denom = h @ W (3-stage ring, ONE barrier per chunk)
        for (int jc = 0; jc < NIN / NCH; jc++) {
            const int j0 = jc * NCH;
            float acc[2][4][4] = {};
            __syncthreads();                 // prior gemm/epilogue done -> safe to stage
            stage_g1(0, 0, j0);
            stage_g1(1, 1, j0);
            const int NK = NOUT / KC;        // 8
            #pragma unroll 1
            for (int kc = 0; kc < NK; kc++) {
                if (kc < NK - 1) CP_WAIT1(); else CP_WAIT0();
                __syncthreads();             // chunk-kc data visible; gemm(kc-1) done by all
                if (kc + 2 < NK) stage_g1(kc + 2, (kc + 2) % NSTG, j0);
                gemm_chunk(sm + (kc % NSTG) * STAGE, acc, lane, wm, wn);
            }
            #pragma unroll
            for (int mt = 0; mt < 2; mt++)
            #pragma unroll
            for (int half = 0; half < 2; half++) {
                const int row = wm * 32 + mt * 16 + mr + half * 8;
                const float xiv = sxinv[row];
                const size_t rowbase = (size_t)(r0 + row) * NIN + j0;
                #pragma unroll
                for (int nt = 0; nt < 4; nt++) {
                    const int jl = wn * 32 + nt * 8 + qc;
                    const float c0 = acc[mt][nt][half * 2], c1 = acc[mt][nt][half * 2 + 1];
                    const float2 xv = *(const float2*)(x + rowbase + jl);
                    const float v0 = __fdividef(xv.x * xiv, c0 + EPSF);
                    const float v1 = __fdividef(xv.y * xiv, c1 + EPSF);
                    uint16_t h0b, l0b, h1b, l1b;
                    bf_split(v0, h0b, l0b); bf_split(v1, h1b, l1b);
                    rhi32[(rowbase + jl) >> 1] = ((uint32_t)h1b << 16) | h0b;
                    rlo32[(rowbase + jl) >> 1] = ((uint32_t)l1b << 16) | l0b;
                }
            }
        }
        __syncthreads();

        // ===== GEMM2: t = ratio @ W^T (3-stage ring); u = h*(1+t)
        for (int nc = 0; nc < NOUT / NCH; nc++) {
            const int nb = nc * NCH;
            float acc[2][4][4] = {};
            __syncthreads();
            stage_g2(0, 0, nb);
            stage_g2(1, 1, nb);
            const int NK = NIN / KC;         // 48
            #pragma unroll 1
            for (int kc = 0; kc < NK; kc++) {
                if (kc < NK - 1) CP_WAIT1(); else CP_WAIT0();
                __syncthreads();
                if (kc + 2 < NK) stage_g2(kc + 2, (kc + 2) % NSTG, nb);
                gemm_chunk(sm + (kc % NSTG) * STAGE, acc, lane, wm, wn);
            }
            #pragma unroll
            for (int mt = 0; mt < 2; mt++)
            #pragma unroll
            for (int half = 0; half < 2; half++) {
                const int row = wm * 32 + mt * 16 + mr + half * 8;
                float partial = 0.f;
                #pragma unroll
                for (int nt = 0; nt < 4; nt++) {
                    const int cl = wn * 32 + nt * 8 + qc;
                    const float t0 = acc[mt][nt][half * 2], t1 = acc[mt][nt][half * 2 + 1];
                    const size_t gi = (size_t)(r0 + row) * NOUT + nb + cl;
                    const float2 hv = *(const float2*)(g_h + gi);
                    const float u0 = hv.x * (1.0f + t0), u1 = hv.y * (1.0f + t1);
                    *(float2*)(g_h + gi) = make_float2(u0, u1);
                    partial += u0 + u1;
                }
                atomicAdd(&srs[row], partial);
            }
        }
        __syncthreads();
        if (tid < MT) ssc[tid] = 1.0f / (srs[tid] + EPSF);
        __syncthreads();

        for (int i = tid; i < MT * NOUT / 2; i += T) {
            const int row = i >> 8, c = i & 255;
            const size_t gi = ((size_t)(r0 + row) * NOUT) / 2 + c;
            float2 hv = ((float2*)g_h)[gi];
            const float sc = ssc[row];
            hv.x *= sc; hv.y *= sc;
            ((float2*)g_h)[gi] = hv;
            uint16_t h0b, l0b, h1b, l1b;
            bf_split(hv.x, h0b, l0b); bf_split(hv.y, h1b, l1b);
            hhi32[gi] = ((uint32_t)h1b << 16) | h0b;
            hlo32[gi] = ((uint32_t)l1b << 16) | l0b;
            if (iter == NITER - 1) ((float2*)out)[gi] = hv;
        }
        __syncthreads();
    }
}

extern "C" void kernel_launch(void* const* d_in, const int* in_sizes, int n_in,
                              void* d_out, int out_size) {
    const float* x = nullptr;
    const float* W = nullptr;
    const float* h0 = nullptr;
    for (int i = 0; i < n_in; i++) {
        if (in_sizes[i] == BATCH * NIN)      x  = (const float*)d_in[i];
        else if (in_sizes[i] == NOUT * NIN)  W  = (const float*)d_in[i];
        else if (in_sizes[i] == NOUT)        h0 = (const float*)d_in[i];
    }
    float* out = (float*)d_out;

    cudaFuncSetAttribute(nnmf_mma_kernel,
                         cudaFuncAttributeMaxDynamicSharedMemorySize, SM_TOTAL);
    nnmf_mma_kernel<<<NB, T, SM_TOTAL>>>(x, W, h0, out);
}

// round 17
// speedup vs baseline: 1.4661x; 1.3015x over previous
#include <cuda_runtime.h>
#include <cuda_fp16.h>
#include <cstdint>
#include <cstring>

#define BATCH 8192
#define NIN   3072
#define NOUT  512
#define EPSF  1e-20f
#define NITER 5
#define MT    64     // rows per block
#define NB    128    // blocks — one wave, co-resident (grid barrier safe)
#define T     256    // threads (8 warps; 2x4 warp grid over 64x128 tile)
#define NCH   128    // N-chunk
#define KC    64     // k-chunk
#define LSCALE 2048.0f
#define LINV   4.8828125e-4f   // 1/2048

// ---- gmem scratch (allocation-free rule) -----------------------------------
__device__ __half g_wh[(size_t)NOUT * NIN];    // W  [n][j] mono fp16
__device__ __half g_wt[(size_t)NIN * NOUT];    // W^T[j][n] mono fp16
__device__ __half g_hh[(size_t)BATCH * NOUT], g_hl[(size_t)BATCH * NOUT]; // h hi + scaled lo
__device__ __half g_rh[(size_t)BATCH * NIN],  g_rl[(size_t)BATCH * NIN];  // ratio hi + scaled lo
__device__ float g_h[(size_t)BATCH * NOUT];
__device__ unsigned g_bar;

// ---- smem: 3-stage cp.async ring; rows padded to 144B -----------------------
#define RS_A   144
#define A_HI   0
#define A_LO   (64 * RS_A)             //  9216
#define B_OF   (2 * 64 * RS_A)         // 18432
#define STAGE  (B_OF + 128 * RS_A)     // 36864
#define NSTG   3
#define SM_XINV (NSTG * STAGE)         // 110592
#define SM_RS   (SM_XINV + 64 * 4)
#define SM_SC   (SM_RS + 64 * 4)
#define SM_TOTAL (SM_SC + 64 * 4)      // 111360 -> 1 block/SM

// split fp32 -> fp16 hi + fp16 lo*2048 (scaled to stay in normal range)
__device__ __forceinline__ void h_split(float v, uint16_t& hi, uint16_t& lo) {
    __half h = __float2half_rn(v);
    __half l = __float2half_rn((v - __half2float(h)) * LSCALE);
    memcpy(&hi, &h, 2); memcpy(&lo, &l, 2);
}
__device__ __forceinline__ uint32_t smem_u32(const void* p) {
    uint32_t a;
    asm("{ .reg .u64 t; cvta.to.shared.u64 t, %1; cvt.u32.u64 %0, t; }" : "=r"(a) : "l"(p));
    return a;
}
__device__ __forceinline__ void cp16(uint32_t saddr, const void* g) {
    asm volatile("cp.async.cg.shared.global [%0], [%1], 16;" :: "r"(saddr), "l"(g));
}
#define CP_COMMIT() asm volatile("cp.async.commit_group;" ::: "memory")
#define CP_WAIT1()  asm volatile("cp.async.wait_group 1;" ::: "memory")
#define CP_WAIT0()  asm volatile("cp.async.wait_group 0;" ::: "memory")

__device__ __forceinline__ void mma_fp16(float c[4], const uint32_t a[4], const uint32_t b[2]) {
    asm volatile(
        "mma.sync.aligned.m16n8k16.row.col.f32.f16.f16.f32 "
        "{%0,%1,%2,%3}, {%4,%5,%6,%7}, {%8,%9}, {%0,%1,%2,%3};"
        : "+f"(c[0]), "+f"(c[1]), "+f"(c[2]), "+f"(c[3])
        : "r"(a[0]), "r"(a[1]), "r"(a[2]), "r"(a[3]), "r"(b[0]), "r"(b[1]));
}

// One 64x128x64 chunk: acch += Ahi*B ; accl += Alo'*B  (2 MMAs per tile).
__device__ __forceinline__ void gemm_chunk(const char* sm, float acch[2][4][4],
                                           float accl[2][4][4], int lane, int wm, int wn) {
    const int mr = lane >> 2;
    const int kq = (lane & 3) * 4;
    #pragma unroll
    for (int ks = 0; ks < 4; ks++) {
        const int kb = ks * 32 + kq;
        uint32_t ah[2][4], al[2][4];
        #pragma unroll
        for (int mt = 0; mt < 2; mt++) {
            const int base = (wm * 32 + mt * 16 + mr) * RS_A + kb;
            ah[mt][0] = *(const uint32_t*)(sm + A_HI + base);
            ah[mt][1] = *(const uint32_t*)(sm + A_HI + base + 8 * RS_A);
            ah[mt][2] = *(const uint32_t*)(sm + A_HI + base + 16);
            ah[mt][3] = *(const uint32_t*)(sm + A_HI + base + 8 * RS_A + 16);
            al[mt][0] = *(const uint32_t*)(sm + A_LO + base);
            al[mt][1] = *(const uint32_t*)(sm + A_LO + base + 8 * RS_A);
            al[mt][2] = *(const uint32_t*)(sm + A_LO + base + 16);
            al[mt][3] = *(const uint32_t*)(sm + A_LO + base + 8 * RS_A + 16);
        }
        #pragma unroll
        for (int nt = 0; nt < 4; nt++) {
            const int base = (wn * 32 + nt * 8 + mr) * RS_A + kb;
            uint32_t b[2];
            b[0] = *(const uint32_t*)(sm + B_OF + base);
            b[1] = *(const uint32_t*)(sm + B_OF + base + 16);
            #pragma unroll
            for (int mt = 0; mt < 2; mt++) {
                mma_fp16(acch[mt][nt], ah[mt], b);
                mma_fp16(accl[mt][nt], al[mt], b);
            }
        }
    }
}

__global__ __launch_bounds__(T, 1) void nnmf_mma_kernel(
    const float* __restrict__ x, const float* __restrict__ W,
    const float* __restrict__ h0, float* __restrict__ out
) {
    extern __shared__ __align__(16) char sm[];
    float* sxinv = (float*)(sm + SM_XINV);
    float* srs   = (float*)(sm + SM_RS);
    float* ssc   = (float*)(sm + SM_SC);
    const uint32_t sb = smem_u32(sm);

    const int tid = threadIdx.x, lane = tid & 31, warp = tid >> 5;
    const int wm = warp >> 2, wn = warp & 3;
    const int r0 = blockIdx.x * MT;

    uint32_t* hh32 = (uint32_t*)g_hh;
    uint32_t* hl32 = (uint32_t*)g_hl;
    uint32_t* rh32 = (uint32_t*)g_rh;
    uint32_t* rl32 = (uint32_t*)g_rl;

    // ---- one-time W + W^T fp16 (grid-cooperative) ----
    for (size_t i = (size_t)blockIdx.x * T + tid; i < (size_t)NOUT * NIN; i += (size_t)NB * T) {
        const int n = (int)(i / NIN), j = (int)(i % NIN);
        __half w = __float2half_rn(W[i]);
        g_wh[i] = w;
        g_wt[(size_t)j * NOUT + n] = w;
    }
    // ---- block-private init: h rows (fp32 + split) and xinv ----
    for (int i = tid; i < MT * NOUT / 2; i += T) {
        const int row = i >> 8, c = i & 255;
        const float v0 = h0[c * 2], v1 = h0[c * 2 + 1];
        uint16_t h0b, l0b, h1b, l1b;
        h_split(v0, h0b, l0b); h_split(v1, h1b, l1b);
        const size_t gi = ((size_t)(r0 + row) * NOUT) / 2 + c;
        ((float2*)g_h)[gi] = make_float2(v0, v1);
        hh32[gi] = ((uint32_t)h1b << 16) | h0b;
        hl32[gi] = ((uint32_t)l1b << 16) | l0b;
    }
    for (int r = warp; r < MT; r += 8) {
        const float* xr = x + (size_t)(r0 + r) * NIN;
        float s = 0.f;
        for (int k = lane; k < NIN; k += 32) s += xr[k];
        #pragma unroll
        for (int o = 16; o; o >>= 1) s += __shfl_xor_sync(~0u, s, o);
        if (lane == 0) sxinv[r] = 1.0f / (s + EPSF);
    }
    __syncthreads();
    if (tid == 0) {   // grid barrier (128 co-resident blocks)
        __threadfence();
        unsigned old = atomicAdd(&g_bar, 1u);
        unsigned target = (old / NB + 1u) * NB;
        while (atomicAdd(&g_bar, 0u) < target) {}
        __threadfence();
    }
    __syncthreads();

    const int mr = lane >> 2, qc = (lane & 3) * 2;

    auto stage_g1 = [&](int kc, int buf, int j0) {
        const int n0 = kc * KC;
        const uint32_t sbase = sb + buf * STAGE;
        for (int idx = tid; idx < 64 * 8; idx += T) {
            const int m = idx >> 3, ch = (idx & 7) * 16;
            const size_t gb = ((size_t)(r0 + m) * NOUT + n0) * 2 + ch;
            cp16(sbase + A_HI + m * RS_A + ch, (const char*)g_hh + gb);
            cp16(sbase + A_LO + m * RS_A + ch, (const char*)g_hl + gb);
        }
        for (int idx = tid; idx < 128 * 8; idx += T) {
            const int j = idx >> 3, ch = (idx & 7) * 16;
            const size_t gb = ((size_t)(j0 + j) * NOUT + n0) * 2 + ch;
            cp16(sbase + B_OF + j * RS_A + ch, (const char*)g_wt + gb);
        }
        CP_COMMIT();
    };
    auto stage_g2 = [&](int kc, int buf, int nb) {
        const int k0 = kc * KC;
        const uint32_t sbase = sb + buf * STAGE;
        for (int idx = tid; idx < 64 * 8; idx += T) {
            const int m = idx >> 3, ch = (idx & 7) * 16;
            const size_t gb = ((size_t)(r0 + m) * NIN + k0) * 2 + ch;
            cp16(sbase + A_HI + m * RS_A + ch, (const char*)g_rh + gb);
            cp16(sbase + A_LO + m * RS_A + ch, (const char*)g_rl + gb);
        }
        for (int idx = tid; idx < 128 * 8; idx += T) {
            const int n = idx >> 3, ch = (idx & 7) * 16;
            const size_t gb = ((size_t)(nb + n) * NIN + k0) * 2 + ch;
            cp16(sbase + B_OF + n * RS_A + ch, (const char*)g_wh + gb);
        }
        CP_COMMIT();
    };

    for (int iter = 0; iter < NITER; iter++) {
        if (tid < MT) srs[tid] = 0.f;

        // ===== GEMM1: denom = h @ W (3-stage ring, one barrier per chunk)
        for (int jc = 0; jc < NIN / NCH; jc++) {
            const int j0 = jc * NCH;
            float acch[2][4][4] = {}, accl[2][4][4] = {};
            __syncthreads();
            stage_g1(0, 0, j0);
            stage_g1(1, 1, j0);
            const int NK = NOUT / KC;        // 8
            #pragma unroll 1
            for (int kc = 0; kc < NK; kc++) {
                if (kc < NK - 1) CP_WAIT1(); else CP_WAIT0();
                __syncthreads();
                if (kc + 2 < NK) stage_g1(kc + 2, (kc + 2) % NSTG, j0);
                gemm_chunk(sm + (kc % NSTG) * STAGE, acch, accl, lane, wm, wn);
            }
            #pragma unroll
            for (int mt = 0; mt < 2; mt++)
            #pragma unroll
            for (int half = 0; half < 2; half++) {
                const int row = wm * 32 + mt * 16 + mr + half * 8;
                const float xiv = sxinv[row];
                const size_t rowbase = (size_t)(r0 + row) * NIN + j0;
                #pragma unroll
                for (int nt = 0; nt < 4; nt++) {
                    const int jl = wn * 32 + nt * 8 + qc;
                    const float c0 = acch[mt][nt][half * 2]     + accl[mt][nt][half * 2]     * LINV;
                    const float c1 = acch[mt][nt][half * 2 + 1] + accl[mt][nt][half * 2 + 1] * LINV;
                    const float2 xv = *(const float2*)(x + rowbase + jl);
                    const float v0 = __fdividef(xv.x * xiv, c0 + EPSF);
                    const float v1 = __fdividef(xv.y * xiv, c1 + EPSF);
                    uint16_t h0b, l0b, h1b, l1b;
                    h_split(v0, h0b, l0b); h_split(v1, h1b, l1b);
                    rh32[(rowbase + jl) >> 1] = ((uint32_t)h1b << 16) | h0b;
                    rl32[(rowbase + jl) >> 1] = ((uint32_t)l1b << 16) | l0b;
                }
            }
        }
        __syncthreads();

        // ===== GEMM2: t = ratio @ W^T (3-stage ring); u = h*(1+t)
        for (int nc = 0; nc < NOUT / NCH; nc++) {
            const int nb = nc * NCH;
            float acch[2][4][4] = {}, accl[2][4][4] = {};
            __syncthreads();
            stage_g2(0, 0, nb);
            stage_g2(1, 1, nb);
            const int NK = NIN / KC;         // 48
            #pragma unroll 1
            for (int kc = 0; kc < NK; kc++) {
                if (kc < NK - 1) CP_WAIT1(); else CP_WAIT0();
                __syncthreads();
                if (kc + 2 < NK) stage_g2(kc + 2, (kc + 2) % NSTG, nb);
                gemm_chunk(sm + (kc % NSTG) * STAGE, acch, accl, lane, wm, wn);
            }
            #pragma unroll
            for (int mt = 0; mt < 2; mt++)
            #pragma unroll
            for (int half = 0; half < 2; half++) {
                const int row = wm * 32 + mt * 16 + mr + half * 8;
                float partial = 0.f;
                #pragma unroll
                for (int nt = 0; nt < 4; nt++) {
                    const int cl = wn * 32 + nt * 8 + qc;
                    const float t0 = acch[mt][nt][half * 2]     + accl[mt][nt][half * 2]     * LINV;
                    const float t1 = acch[mt][nt][half * 2 + 1] + accl[mt][nt][half * 2 + 1] * LINV;
                    const size_t gi = (size_t)(r0 + row) * NOUT + nb + cl;
                    const float2 hv = *(const float2*)(g_h + gi);
                    const float u0 = hv.x * (1.0f + t0), u1 = hv.y * (1.0f + t1);
                    *(float2*)(g_h + gi) = make_float2(u0, u1);
                    partial += u0 + u1;
                }
                atomicAdd(&srs[row], partial);
            }
        }
        __syncthreads();
        if (tid < MT) ssc[tid] = 1.0f / (srs[tid] + EPSF);
        __syncthreads();

        for (int i = tid; i < MT * NOUT / 2; i += T) {
            const int row = i >> 8, c = i & 255;
            const size_t gi = ((size_t)(r0 + row) * NOUT) / 2 + c;
            float2 hv = ((float2*)g_h)[gi];
            const float sc = ssc[row];
            hv.x *= sc; hv.y *= sc;
            ((float2*)g_h)[gi] = hv;
            uint16_t h0b, l0b, h1b, l1b;
            h_split(hv.x, h0b, l0b); h_split(hv.y, h1b, l1b);
            hh32[gi] = ((uint32_t)h1b << 16) | h0b;
            hl32[gi] = ((uint32_t)l1b << 16) | l0b;
            if (iter == NITER - 1) ((float2*)out)[gi] = hv;
        }
        __syncthreads();
    }
}

extern "C" void kernel_launch(void* const* d_in, const int* in_sizes, int n_in,
                              void* d_out, int out_size) {
    const float* x = nullptr;
    const float* W = nullptr;
    const float* h0 = nullptr;
    for (int i = 0; i < n_in; i++) {
        if (in_sizes[i] == BATCH * NIN)      x  = (const float*)d_in[i];
        else if (in_sizes[i] == NOUT * NIN)  W  = (const float*)d_in[i];
        else if (in_sizes[i] == NOUT)        h0 = (const float*)d_in[i];
    }
    float* out = (float*)d_out;

    cudaFuncSetAttribute(nnmf_mma_kernel,
                         cudaFuncAttributeMaxDynamicSharedMemorySize, SM_TOTAL);
    nnmf_mma_kernel<<<NB, T, SM_TOTAL>>>(x, W, h0, out);
}